// round 14
// baseline (speedup 1.0000x reference)
#include <cuda_runtime.h>

// Problem constants (fixed shapes)
#define Kc    100
#define Dc    64
#define TPB   512            // 16 warps, 4 per SMSP
#define WPB   16
#define NPAIR 8              // warp pairs per block
#define NBLK  152
#define TOTP  (NBLK * NPAIR) // 1216 warp pairs
#define WTBLF (Kc * 32)      // floats per warp sum table (row = 32 dims x 4B)
#define SQOFF (WPB * WTBLF)           // float offset of (sq,cnt) region: 51200
#define SMFLT (SQOFF + WPB * Kc * 2)  // 54400 floats = 217,600 B
#define UNR   4              // points per batch (4 half-points per warp instr)
#define PIPE  9              // batches in flight per warp

// Global scratch (zero-init at load; re-zeroed by findb each replay)
__device__ float g_S1[Kc * Dc];
__device__ float g_S2[Kc];
__device__ float g_cnt[Kc];
__device__ float g_At[Dc * Kc];   // centroids, transposed [d][c]
__device__ float g_Si[Kc];

__device__ __forceinline__ unsigned smem_u32(const void* p) {
    unsigned r;
    asm("{ .reg .u64 t; cvta.to.shared.u64 t, %1; cvt.u32.u64 %0, t; }"
        : "=r"(r) : "l"(p));
    return r;
}

// ---------------------------------------------------------------------------
// Kernel B: main streaming pass.
// Warp pair (2w,2w+1): half=w&1 owns dims [half*32, half*32+32).
// NEW mapping: lane = (u=lane>>3 point-in-batch, sub=lane&7 dim-chunk);
// each lane owns 4 consecutive dims -> float4 everywhere:
//   1 LDG.128 stages 4 half-points; 1 LDS.128/STS.128 RMWs 4 table rows.
// Per-point |x|^2 half-partial: 4 FMA + 3 in-group shuffles; group leader
// (sub==0) RMWs the per-warp (sq,cnt) side row (+0.5 cnt per warp).
// ---------------------------------------------------------------------------
__global__ __launch_bounds__(TPB, 1)
void pass1_kernel(const float* __restrict__ data,
                  const int* __restrict__ ci, int N) {
    extern __shared__ float sm[];
    const int tid  = threadIdx.x;
    const int w    = tid >> 5;
    const int lane = tid & 31;
    const int half = w & 1;
    const int u    = lane >> 3;      // point within batch (0..3)
    const int sub  = lane & 7;       // 4-dim chunk within half (0..7)

    float4* z = (float4*)sm;
    for (int i = tid; i < (SMFLT >> 2); i += TPB)
        z[i] = make_float4(0.f, 0.f, 0.f, 0.f);
    __syncthreads();

    const unsigned smb  = smem_u32(sm);
    const unsigned sumb = smb + (unsigned)w * (WTBLF * 4) + (unsigned)sub * 16;
    const unsigned sqb  = smb + SQOFF * 4 + (unsigned)w * (Kc * 8);

    const int gp    = blockIdx.x * NPAIR + (w >> 1);
    const int chunk = (((N + TOTP - 1) / TOTP) + 15) & ~15;  // 16-aligned
    const int begin = gp * chunk;
    const int end   = min(N, begin + chunk);
    const int doff4 = half * 32 + 4 * sub;   // first of this lane's 4 dims

    int    cb[PIPE][UNR];
    float4 vb[PIPE];

    auto stage = [&](int j, int base) {
        const int4 cc = *(const int4*)&ci[base];   // 16B-aligned
        cb[j][0] = cc.x; cb[j][1] = cc.y; cb[j][2] = cc.z; cb[j][3] = cc.w;
        vb[j] = *(const float4*)&data[(base + u) * 64 + doff4]; // LDG.128
    };

    auto process = [&](int j) {
        const int c0 = cb[j][0], c1 = cb[j][1], c2 = cb[j][2], c3 = cb[j][3];
        const float4 v = vb[j];
        const int cu = (u & 2) ? ((u & 1) ? c3 : c2) : ((u & 1) ? c1 : c0);
        const unsigned ad  = sumb + ((unsigned)cu << 7);
        const unsigned sqa = sqb + (unsigned)cu * 8u;

        // |x|^2 over this lane's 4 dims, then 8-lane in-group reduce.
        float q = v.x * v.x;
        q = fmaf(v.y, v.y, q);
        q = fmaf(v.z, v.z, q);
        q = fmaf(v.w, v.w, q);
        q += __shfl_xor_sync(~0u, q, 4);
        q += __shfl_xor_sync(~0u, q, 2);
        q += __shfl_xor_sync(~0u, q, 1);   // all 8 lanes: 32-dim half partial

        const bool clash = (c0 == c1) | (c0 == c2) | (c0 == c3)
                         | (c1 == c2) | (c1 == c3) | (c2 == c3);
        if (!clash) {   // 4 distinct rows: one vectorized RMW covers all
            float a0, a1, a2, a3;
            asm volatile("ld.shared.v4.f32 {%0,%1,%2,%3},[%4];"
                         : "=f"(a0), "=f"(a1), "=f"(a2), "=f"(a3) : "r"(ad));
            float s0 = 0.f, s1 = 0.f;
            if (sub == 0)
                asm volatile("ld.shared.v2.f32 {%0,%1},[%2];"
                             : "=f"(s0), "=f"(s1) : "r"(sqa));
            a0 += v.x; a1 += v.y; a2 += v.z; a3 += v.w;
            s0 += q;   s1 += 0.5f;   // half cnt per warp; pair total = 1.0
            asm volatile("st.shared.v4.f32 [%0],{%1,%2,%3,%4};"
                         :: "r"(ad), "f"(a0), "f"(a1), "f"(a2), "f"(a3)
                         : "memory");
            if (sub == 0)
                asm volatile("st.shared.v2.f32 [%0],{%1,%2};"
                             :: "r"(sqa), "f"(s0), "f"(s1) : "memory");
        } else {        // rare (~6%): serialize the 4 groups (program order
                        // within the warp makes duplicate rows accumulate)
#pragma unroll
            for (int g = 0; g < 4; g++) {
                if (u == g) {
                    float a0, a1, a2, a3;
                    asm volatile("ld.shared.v4.f32 {%0,%1,%2,%3},[%4];"
                                 : "=f"(a0), "=f"(a1), "=f"(a2), "=f"(a3)
                                 : "r"(ad));
                    a0 += v.x; a1 += v.y; a2 += v.z; a3 += v.w;
                    asm volatile("st.shared.v4.f32 [%0],{%1,%2,%3,%4};"
                                 :: "r"(ad), "f"(a0), "f"(a1), "f"(a2), "f"(a3)
                                 : "memory");
                    if (sub == 0) {
                        float s0, s1;
                        asm volatile("ld.shared.v2.f32 {%0,%1},[%2];"
                                     : "=f"(s0), "=f"(s1) : "r"(sqa));
                        s0 += q;
                        s1 += 0.5f;
                        asm volatile("st.shared.v2.f32 [%0],{%1,%2};"
                                     :: "r"(sqa), "f"(s0), "f"(s1) : "memory");
                    }
                }
            }
        }
    };

    const int nb = (begin < end) ? (end - begin) / UNR : 0;

#pragma unroll
    for (int j = 0; j < PIPE; j++)
        if (j < nb) stage(j, begin + j * UNR);

    int b = 0;
    for (; b + PIPE <= nb; b += PIPE) {
#pragma unroll
        for (int j = 0; j < PIPE; j++) {
            process(j);
            const int nxt = b + j + PIPE;
            if (nxt < nb) stage(j, begin + nxt * UNR);
        }
    }
#pragma unroll
    for (int j = 0; j < PIPE; j++)
        if (b + j < nb) process(j);

    for (int p = begin + nb * UNR; p < end; p++) {   // tail (<4 points)
        const int c0 = ci[p];
        // all lanes load the same half-point (groups redundant, convergent)
        const float4 v = *(const float4*)&data[p * 64 + doff4];
        float q = v.x * v.x;
        q = fmaf(v.y, v.y, q);
        q = fmaf(v.z, v.z, q);
        q = fmaf(v.w, v.w, q);
        q += __shfl_xor_sync(~0u, q, 4);
        q += __shfl_xor_sync(~0u, q, 2);
        q += __shfl_xor_sync(~0u, q, 1);
        if (u == 0) {    // only group 0 commits
            const unsigned ad = sumb + ((unsigned)c0 << 7);
            float a0, a1, a2, a3;
            asm volatile("ld.shared.v4.f32 {%0,%1,%2,%3},[%4];"
                         : "=f"(a0), "=f"(a1), "=f"(a2), "=f"(a3) : "r"(ad));
            a0 += v.x; a1 += v.y; a2 += v.z; a3 += v.w;
            asm volatile("st.shared.v4.f32 [%0],{%1,%2,%3,%4};"
                         :: "r"(ad), "f"(a0), "f"(a1), "f"(a2), "f"(a3)
                         : "memory");
            if (sub == 0) {
                const unsigned sqa = sqb + (unsigned)c0 * 8u;
                float s0, s1;
                asm volatile("ld.shared.v2.f32 {%0,%1},[%2];"
                             : "=f"(s0), "=f"(s1) : "r"(sqa));
                s0 += q;
                s1 += 0.5f;
                asm volatile("st.shared.v2.f32 [%0],{%1,%2};"
                             :: "r"(sqa), "f"(s0), "f"(s1) : "memory");
            }
        }
    }
    __syncthreads();

    // Combine: S1[c][d] = sum over the 8 warps of parity (d>=32).
    // Table linear layout per warp: [c][d-within-half] — same as before.
    for (int i = tid; i < Kc * Dc; i += TPB) {
        const int c = i >> 6, d = i & 63;
        const int par = (d >> 5), l = d & 31;
        float s = 0.f;
#pragma unroll
        for (int pp = 0; pp < NPAIR; pp++)
            s += sm[(pp * 2 + par) * WTBLF + c * 32 + l];
        atomicAdd(&g_S1[c * Dc + d], s);
    }
    // S2[c], cnt[c] from all 16 warps' (sq,cnt) tables.
    if (tid < Kc) {
        float s = 0.f, ct = 0.f;
#pragma unroll
        for (int ww = 0; ww < WPB; ww++) {
            s  += sm[SQOFF + ww * Kc * 2 + tid * 2];
            ct += sm[SQOFF + ww * Kc * 2 + tid * 2 + 1];
        }
        atomicAdd(&g_S2[tid], s);
        atomicAdd(&g_cnt[tid], ct);
    }
}

// ---------------------------------------------------------------------------
// Kernel C: centroids + Si (accumulator re-zero happens in findb).
// ---------------------------------------------------------------------------
__global__ void finpre_kernel(float* __restrict__ out) {
    __shared__ float At[Dc * Kc];   // [d][c]
    const int tid = threadIdx.x;    // 512
    for (int i = tid; i < Kc * Dc; i += blockDim.x) {
        const int c = i / Dc, d = i - c * Dc;
        const float a = (0.001f + g_S1[i]) / (1.0f + g_cnt[c]);
        At[d * Kc + c] = a;
        g_At[d * Kc + c] = a;
    }
    __syncthreads();
    if (tid < Kc) {
        float nrm = 0.f, sa = 0.f;
#pragma unroll
        for (int d = 0; d < Dc; d++) {
            const float a = At[d * Kc + tid];
            nrm += a * a;
            sa  += a;
        }
        const float n  = g_cnt[tid];
        const float cs = 1.f + n;
        // dot(A, S1) = cs*|A|^2 - 0.001*sum(A)  (S1 = A*cs - 0.001 per dim)
        const float dot = cs * nrm - 0.001f * sa;
        const float val = (0.001f + g_S2[tid] - 2.f * dot + n * nrm) / cs;
        g_Si[tid] = sqrtf(fmaxf(val, 0.f));
    }
    if (tid == 0) out[0] = 0.f;
}

// ---------------------------------------------------------------------------
// Kernel D: one block per cluster row; row-max of Rij; atomic sum of maxima.
// Block c also re-zeroes accumulator slice c for the next graph replay.
// ---------------------------------------------------------------------------
__global__ void findb_kernel(float* __restrict__ out) {
    __shared__ float At[Dc * Kc];
    __shared__ float Sis[Kc];
    __shared__ float wmax[4];
    const int tid = threadIdx.x;    // 128
    const int c   = blockIdx.x;     // 0..99
    const float4* a4 = (const float4*)g_At;
    float4* s4 = (float4*)At;
    for (int i = tid; i < (Dc * Kc) >> 2; i += blockDim.x) s4[i] = a4[i];
    if (tid < Kc) Sis[tid] = g_Si[tid];
    // Re-zero this cluster's accumulator slice (already consumed by finpre).
    if (tid < Dc) g_S1[c * Dc + tid] = 0.f;
    if (tid == Dc) { g_S2[c] = 0.f; g_cnt[c] = 0.f; }
    __syncthreads();
    float m = 0.f;
    if (tid < Kc && tid != c) {
        const int j = tid;
        float ss = 0.f;
#pragma unroll
        for (int d = 0; d < Dc; d++) {
            const float df = At[d * Kc + c] - At[d * Kc + j];
            ss = fmaf(df, df, ss);
        }
        m = (Sis[c] + Sis[j]) / sqrtf(ss);
    }
#pragma unroll
    for (int o = 16; o > 0; o >>= 1) m = fmaxf(m, __shfl_xor_sync(~0u, m, o));
    if ((tid & 31) == 0) wmax[tid >> 5] = m;
    __syncthreads();
    if (tid == 0) {
        const float mm = fmaxf(fmaxf(wmax[0], wmax[1]), fmaxf(wmax[2], wmax[3]));
        atomicAdd(out, mm * (1.0f / (float)Kc));
    }
}

// ---------------------------------------------------------------------------
extern "C" void kernel_launch(void* const* d_in, const int* in_sizes, int n_in,
                              void* d_out, int out_size) {
    const float* data = (const float*)d_in[0];
    const int*   clus = (const int*)d_in[1];   // int32 labels (JAX x64 disabled)
    const int N = in_sizes[1];                 // 2,000,000

    const size_t smem = (size_t)SMFLT * sizeof(float);   // 217,600 B
    cudaFuncSetAttribute(pass1_kernel,
                         cudaFuncAttributeMaxDynamicSharedMemorySize, (int)smem);

    pass1_kernel <<<NBLK, TPB, smem>>>(data, clus, N);
    finpre_kernel<<<1, 512>>>((float*)d_out);
    findb_kernel <<<Kc, 128>>>((float*)d_out);
}

// round 15
// speedup vs baseline: 1.3724x; 1.3724x over previous
#include <cuda_runtime.h>

// Problem constants (fixed shapes)
#define Kc    100
#define Dc    64
#define TPB   512            // 16 warps, 4 per SMSP
#define WPB   16
#define NPAIR 8              // warp pairs per block
#define NBLK  152
#define TOTP  (NBLK * NPAIR) // 1216 warp pairs
#define WTBLF (Kc * 32)      // floats per warp sum table (4B slot, lane=dim)
#define SQOFF (WPB * WTBLF)           // float offset of (sq,cnt) region: 51200
#define SMFLT (SQOFF + WPB * Kc * 2)  // 54400 floats = 217,600 B
#define UNR   4              // points per batch
#define PIPE  10             // batches in flight per warp (R12 had 8)

// Global scratch (zero-init at load; re-zeroed by findb each replay)
__device__ float g_S1[Kc * Dc];
__device__ float g_S2[Kc];
__device__ float g_cnt[Kc];
__device__ float g_At[Dc * Kc];   // centroids, transposed [d][c]
__device__ float g_Si[Kc];

__device__ __forceinline__ unsigned smem_u32(const void* p) {
    unsigned r;
    asm("{ .reg .u64 t; cvta.to.shared.u64 t, %1; cvt.u32.u64 %0, t; }"
        : "=r"(r) : "l"(p));
    return r;
}

// ---------------------------------------------------------------------------
// Kernel B: main streaming pass (counts folded in; no separate histogram).
// Warp pair (2w,2w+1): half=w&1 owns dims [half*32,half*32+32); lane owns ONE
// dim -> 4B sum slot. Per-batch |x|^2 totals via a 4-value butterfly;
// designated lanes {0,8,16,24} RMW the per-warp (sq,cnt) side table with one
// v2 access. Each warp of a pair adds 0.5 per point (pair total = 1.0).
// ---------------------------------------------------------------------------
__global__ __launch_bounds__(TPB, 1)
void pass1_kernel(const float* __restrict__ data,
                  const int* __restrict__ ci, int N) {
    extern __shared__ float sm[];
    const int tid  = threadIdx.x;
    const int w    = tid >> 5;
    const int lane = tid & 31;
    const int half = w & 1;

    float4* z = (float4*)sm;
    for (int i = tid; i < (SMFLT >> 2); i += TPB)
        z[i] = make_float4(0.f, 0.f, 0.f, 0.f);
    __syncthreads();

    const unsigned smb  = smem_u32(sm);
    const unsigned sumb = smb + (unsigned)w * (WTBLF * 4) + (unsigned)lane * 4;
    const unsigned sqb  = smb + SQOFF * 4 + (unsigned)w * (Kc * 8);

    const int gp    = blockIdx.x * NPAIR + (w >> 1);
    const int chunk = (((N + TOTP - 1) / TOTP) + 15) & ~15;  // 16-aligned
    const int begin = gp * chunk;
    const int end   = min(N, begin + chunk);
    const int doff  = half * 32 + lane;   // this thread's dim

    const bool b3 = (lane & 8) != 0, b4 = (lane & 16) != 0;
    const bool desig = (lane & 7) == 0;   // lanes 0,8,16,24

    int   cb[PIPE][UNR];
    float vb[PIPE][UNR];

    auto stage = [&](int j, int base) {
        const int4 cc = *(const int4*)&ci[base];   // 16B-aligned
        cb[j][0] = cc.x; cb[j][1] = cc.y; cb[j][2] = cc.z; cb[j][3] = cc.w;
#pragma unroll
        for (int u = 0; u < UNR; u++)
            vb[j][u] = data[(base + u) * 64 + doff];   // 128B/warp coalesced
    };

    auto process = [&](int j) {
        int*   c = cb[j];
        float* v = vb[j];
        float  r[UNR];
        unsigned addr[UNR];
#pragma unroll
        for (int u = 0; u < UNR; u++) {
            r[u]    = v[u] * v[u];                 // per-lane |x|^2 partial
            addr[u] = sumb + ((unsigned)c[u] << 7);
        }
        // 4-value butterfly: reduce r0..r3 across 32 lanes simultaneously.
        // Result: lanes 0-7 tot(r0), 8-15 tot(r2), 16-23 tot(r1), 24-31 tot(r3).
        float t, v01, v23, val;
        t   = __shfl_xor_sync(~0u, b4 ? r[0] : r[1], 16);
        v01 = (b4 ? r[1] : r[0]) + t;
        t   = __shfl_xor_sync(~0u, b4 ? r[2] : r[3], 16);
        v23 = (b4 ? r[3] : r[2]) + t;
        t   = __shfl_xor_sync(~0u, b3 ? v01 : v23, 8);
        val = (b3 ? v23 : v01) + t;
        val += __shfl_xor_sync(~0u, val, 4);
        val += __shfl_xor_sync(~0u, val, 2);
        val += __shfl_xor_sync(~0u, val, 1);

        bool clash = false;
#pragma unroll
        for (int u = 0; u < UNR - 1; u++)
#pragma unroll
            for (int k = u + 1; k < UNR; k++) clash |= (c[u] == c[k]);

        if (!clash) {   // distinct clusters: batch all LDS before any STS
            // designated lane's point: lane0->0, lane8->2, lane16->1, lane24->3
            const int cg = b4 ? (b3 ? c[3] : c[1]) : (b3 ? c[2] : c[0]);
            const unsigned sqa = sqb + (unsigned)cg * 8u;
            float a[UNR];
#pragma unroll
            for (int u = 0; u < UNR; u++)
                asm volatile("ld.shared.f32 %0,[%1];" : "=f"(a[u]) : "r"(addr[u]));
            float s0 = 0.f, s1 = 0.f;
            if (desig)
                asm volatile("ld.shared.v2.f32 {%0,%1},[%2];"
                             : "=f"(s0), "=f"(s1) : "r"(sqa));
#pragma unroll
            for (int u = 0; u < UNR; u++) a[u] += v[u];
            s0 += val;
            s1 += 0.5f;   // half per warp; pair total = 1.0 per point
#pragma unroll
            for (int u = 0; u < UNR; u++)
                asm volatile("st.shared.f32 [%0],%1;"
                             :: "r"(addr[u]), "f"(a[u]) : "memory");
            if (desig)
                asm volatile("st.shared.v2.f32 [%0],{%1,%2};"
                             :: "r"(sqa), "f"(s0), "f"(s1) : "memory");
        } else {        // rare (~6%): merge duplicates forward, serial chains
            float rt[UNR], cn[UNR];
            rt[0] = __shfl_sync(~0u, val, 0);
            rt[1] = __shfl_sync(~0u, val, 16);
            rt[2] = __shfl_sync(~0u, val, 8);
            rt[3] = __shfl_sync(~0u, val, 24);
#pragma unroll
            for (int u = 0; u < UNR; u++) cn[u] = 0.5f;  // half per warp
            bool live[UNR];
#pragma unroll
            for (int u = 0; u < UNR; u++) live[u] = true;
#pragma unroll
            for (int u = 0; u < UNR - 1; u++) {
                bool moved = false;
#pragma unroll
                for (int k = u + 1; k < UNR; k++) {
                    bool m = (c[u] == c[k]) && !moved;
                    if (m) { v[k] += v[u]; rt[k] += rt[u]; cn[k] += cn[u]; }
                    moved = moved || m;
                }
                live[u] = !moved;
            }
#pragma unroll
            for (int u = 0; u < UNR; u++) {
                if (live[u]) {
                    float a;
                    asm volatile("ld.shared.f32 %0,[%1];" : "=f"(a) : "r"(addr[u]));
                    a += v[u];
                    asm volatile("st.shared.f32 [%0],%1;"
                                 :: "r"(addr[u]), "f"(a) : "memory");
                    // collapsed all-lane v2 RMW (same addr, same values)
                    const unsigned sqa = sqb + (unsigned)c[u] * 8u;
                    float s0, s1;
                    asm volatile("ld.shared.v2.f32 {%0,%1},[%2];"
                                 : "=f"(s0), "=f"(s1) : "r"(sqa));
                    s0 += rt[u];
                    s1 += cn[u];
                    asm volatile("st.shared.v2.f32 [%0],{%1,%2};"
                                 :: "r"(sqa), "f"(s0), "f"(s1) : "memory");
                }
            }
        }
    };

    const int nb = (begin < end) ? (end - begin) / UNR : 0;

#pragma unroll
    for (int j = 0; j < PIPE; j++)
        if (j < nb) stage(j, begin + j * UNR);

    int b = 0;
    for (; b + PIPE <= nb; b += PIPE) {
#pragma unroll
        for (int j = 0; j < PIPE; j++) {
            process(j);
            const int nxt = b + j + PIPE;
            if (nxt < nb) stage(j, begin + nxt * UNR);
        }
    }
#pragma unroll
    for (int j = 0; j < PIPE; j++)
        if (b + j < nb) process(j);

    for (int p = begin + nb * UNR; p < end; p++) {   // tail (<4 points)
        const int c0 = ci[p];
        const float vv = data[p * 64 + doff];
        float rr = vv * vv;
#pragma unroll
        for (int o = 16; o > 0; o >>= 1)
            rr += __shfl_xor_sync(~0u, rr, o);
        const unsigned ad = sumb + ((unsigned)c0 << 7);
        float a;
        asm volatile("ld.shared.f32 %0,[%1];" : "=f"(a) : "r"(ad));
        a += vv;
        asm volatile("st.shared.f32 [%0],%1;" :: "r"(ad), "f"(a) : "memory");
        const unsigned sqa = sqb + (unsigned)c0 * 8u;   // all lanes same addr
        float s0, s1;
        asm volatile("ld.shared.v2.f32 {%0,%1},[%2];"
                     : "=f"(s0), "=f"(s1) : "r"(sqa));
        s0 += rr;
        s1 += 0.5f;   // half per warp; pair total = 1.0 per point
        asm volatile("st.shared.v2.f32 [%0],{%1,%2};"
                     :: "r"(sqa), "f"(s0), "f"(s1) : "memory");
    }
    __syncthreads();

    // Combine: S1[c][d] = sum over the 8 warps of parity (d>=32).
    for (int i = tid; i < Kc * Dc; i += TPB) {
        const int c = i >> 6, d = i & 63;
        const int par = (d >> 5), l = d & 31;
        float s = 0.f;
#pragma unroll
        for (int pp = 0; pp < NPAIR; pp++)
            s += sm[(pp * 2 + par) * WTBLF + c * 32 + l];
        atomicAdd(&g_S1[c * Dc + d], s);
    }
    // S2[c], cnt[c] from all 16 warps' (sq,cnt) tables.
    if (tid < Kc) {
        float s = 0.f, ct = 0.f;
#pragma unroll
        for (int ww = 0; ww < WPB; ww++) {
            s  += sm[SQOFF + ww * Kc * 2 + tid * 2];
            ct += sm[SQOFF + ww * Kc * 2 + tid * 2 + 1];
        }
        atomicAdd(&g_S2[tid], s);
        atomicAdd(&g_cnt[tid], ct);
    }
}

// ---------------------------------------------------------------------------
// Kernel C: centroids + Si (accumulator re-zero happens in findb).
// ---------------------------------------------------------------------------
__global__ void finpre_kernel(float* __restrict__ out) {
    __shared__ float At[Dc * Kc];   // [d][c]
    const int tid = threadIdx.x;    // 512
    for (int i = tid; i < Kc * Dc; i += blockDim.x) {
        const int c = i / Dc, d = i - c * Dc;
        const float a = (0.001f + g_S1[i]) / (1.0f + g_cnt[c]);
        At[d * Kc + c] = a;
        g_At[d * Kc + c] = a;
    }
    __syncthreads();
    if (tid < Kc) {
        float nrm = 0.f, sa = 0.f;
#pragma unroll
        for (int d = 0; d < Dc; d++) {
            const float a = At[d * Kc + tid];
            nrm += a * a;
            sa  += a;
        }
        const float n  = g_cnt[tid];
        const float cs = 1.f + n;
        // dot(A, S1) = cs*|A|^2 - 0.001*sum(A)  (S1 = A*cs - 0.001 per dim)
        const float dot = cs * nrm - 0.001f * sa;
        const float val = (0.001f + g_S2[tid] - 2.f * dot + n * nrm) / cs;
        g_Si[tid] = sqrtf(fmaxf(val, 0.f));
    }
    if (tid == 0) out[0] = 0.f;
}

// ---------------------------------------------------------------------------
// Kernel D: one block per cluster row; row-max of Rij; atomic sum of maxima.
// Block c also re-zeroes accumulator slice c for the next graph replay.
// ---------------------------------------------------------------------------
__global__ void findb_kernel(float* __restrict__ out) {
    __shared__ float At[Dc * Kc];
    __shared__ float Sis[Kc];
    __shared__ float wmax[4];
    const int tid = threadIdx.x;    // 128
    const int c   = blockIdx.x;     // 0..99
    const float4* a4 = (const float4*)g_At;
    float4* s4 = (float4*)At;
    for (int i = tid; i < (Dc * Kc) >> 2; i += blockDim.x) s4[i] = a4[i];
    if (tid < Kc) Sis[tid] = g_Si[tid];
    // Re-zero this cluster's accumulator slice (already consumed by finpre).
    if (tid < Dc) g_S1[c * Dc + tid] = 0.f;
    if (tid == Dc) { g_S2[c] = 0.f; g_cnt[c] = 0.f; }
    __syncthreads();
    float m = 0.f;
    if (tid < Kc && tid != c) {
        const int j = tid;
        float ss = 0.f;
#pragma unroll
        for (int d = 0; d < Dc; d++) {
            const float df = At[d * Kc + c] - At[d * Kc + j];
            ss = fmaf(df, df, ss);
        }
        m = (Sis[c] + Sis[j]) / sqrtf(ss);
    }
#pragma unroll
    for (int o = 16; o > 0; o >>= 1) m = fmaxf(m, __shfl_xor_sync(~0u, m, o));
    if ((tid & 31) == 0) wmax[tid >> 5] = m;
    __syncthreads();
    if (tid == 0) {
        const float mm = fmaxf(fmaxf(wmax[0], wmax[1]), fmaxf(wmax[2], wmax[3]));
        atomicAdd(out, mm * (1.0f / (float)Kc));
    }
}

// ---------------------------------------------------------------------------
extern "C" void kernel_launch(void* const* d_in, const int* in_sizes, int n_in,
                              void* d_out, int out_size) {
    const float* data = (const float*)d_in[0];
    const int*   clus = (const int*)d_in[1];   // int32 labels (JAX x64 disabled)
    const int N = in_sizes[1];                 // 2,000,000

    const size_t smem = (size_t)SMFLT * sizeof(float);   // 217,600 B
    cudaFuncSetAttribute(pass1_kernel,
                         cudaFuncAttributeMaxDynamicSharedMemorySize, (int)smem);

    pass1_kernel <<<NBLK, TPB, smem>>>(data, clus, N);
    finpre_kernel<<<1, 512>>>((float*)d_out);
    findb_kernel <<<Kc, 128>>>((float*)d_out);
}